// round 9
// baseline (speedup 1.0000x reference)
#include <cuda_runtime.h>
#include <math.h>
#include <stdint.h>

// Problem constants (fixed-shape problem)
#define NA_N   40000
#define NB_N   40000
#define EPS_LN 1e-5f

#define WARPS_PER_BLK 12
#define EDGE_BLOCKS   148          // per edge type
#define THREADS_BLK   (WARPS_PER_BLK * 32)
#define PAIR_STRIDE   (EDGE_BLOCKS * WARPS_PER_BLK * 2)
#define NODE_STRIDE   (148 * WARPS_PER_BLK)

// Scratch (static device arrays; no runtime alloc)
// g_acc uses pair-interleaved "position" layout: pos(c) = c<32 ? 2c : 2(c-32)+1
__device__ float g_acc[2ull * NA_N * 256ull];
__device__ int   g_cnt[2 * NA_N];
// Precomputed per-(type,node) projections (canonical channel order):
//   g_dstqkv[t][n][0:256)=q, [256:512)=k, [512:768)=v
//   g_srckv [t][n][0:256)=k, [256:512)=v   (fused (Wk·Wb)x form)
__device__ float g_dstqkv[2ull * NA_N * 768ull];
__device__ float g_srckv [2ull * NA_N * 512ull];
// Fused src weights: [t][c][128] (k|v feature columns), biases [t][128]
__device__ float g_wfuse[2 * 64 * 128];
__device__ float g_bfuse[2 * 128];

// ---------------------------------------------------------------------------
// helpers
// ---------------------------------------------------------------------------
__device__ __forceinline__ int posof(int c) { return (c < 32) ? (2 * c) : (2 * (c - 32) + 1); }

__device__ __forceinline__ float warp_sum(float v) {
#pragma unroll
    for (int o = 16; o; o >>= 1) v += __shfl_xor_sync(0xffffffffu, v, o);
    return v;
}
__device__ __forceinline__ float warp_max(float v) {
#pragma unroll
    for (int o = 16; o; o >>= 1) v = fmaxf(v, __shfl_xor_sync(0xffffffffu, v, o));
    return v;
}

// Permuted GEMM core: activations in position layout, weights [p][64] with both
// dims permuted. Lane owns output positions (2*lane, 2*lane+1) = channels
// (lane, lane+32): weight read is one LDS.64; input rows broadcast float4.
template <int S>
__device__ __forceinline__ void mm64p_core(const float* __restrict__ in, int in_stride,
                                           const float* __restrict__ Wt,
                                           int lane, float2* acc) {
#pragma unroll
    for (int s = 0; s < S; s++) { acc[s].x = 0.f; acc[s].y = 0.f; }
#pragma unroll
    for (int c4 = 0; c4 < 16; c4++) {
        float4 xv[S];
#pragma unroll
        for (int s = 0; s < S; s++)
            xv[s] = *reinterpret_cast<const float4*>(in + s * in_stride + (c4 << 2));
#pragma unroll
        for (int j = 0; j < 4; j++) {
            const float2 w = *reinterpret_cast<const float2*>(
                Wt + (((c4 << 2) + j) << 6) + 2 * lane);
#pragma unroll
            for (int s = 0; s < S; s++) {
                float xx = (j == 0) ? xv[s].x : (j == 1) ? xv[s].y : (j == 2) ? xv[s].z : xv[s].w;
                acc[s].x = fmaf(xx, w.x, acc[s].x);
                acc[s].y = fmaf(xx, w.y, acc[s].y);
            }
        }
    }
}

// Canonical multi-matrix sweep (used by precompute kernels, unchanged semantics)
template <int M, int WSTRIDE>
__device__ __forceinline__ void mmqkv_core(const float* __restrict__ in,
                                           const float* __restrict__ Wq, const int* woff,
                                           int lane, float (*a0)[4], float (*a1)[4]) {
#pragma unroll
    for (int m = 0; m < M; m++)
#pragma unroll
        for (int s = 0; s < 4; s++) { a0[m][s] = 0.f; a1[m][s] = 0.f; }
#pragma unroll
    for (int c4 = 0; c4 < 16; c4++) {
        float4 xv[4];
#pragma unroll
        for (int s = 0; s < 4; s++)
            xv[s] = *reinterpret_cast<const float4*>(in + s * 64 + (c4 << 2));
#pragma unroll
        for (int j = 0; j < 4; j++) {
            const float* wrow = Wq + ((c4 << 2) + j) * WSTRIDE;
            float w0[M], w1[M];
#pragma unroll
            for (int m = 0; m < M; m++) {
                w0[m] = wrow[woff[m] + lane];
                w1[m] = wrow[woff[m] + lane + 32];
            }
#pragma unroll
            for (int s = 0; s < 4; s++) {
                float xx = (j == 0) ? xv[s].x : (j == 1) ? xv[s].y : (j == 2) ? xv[s].z : xv[s].w;
#pragma unroll
                for (int m = 0; m < M; m++) {
                    a0[m][s] = fmaf(xx, w0[m], a0[m][s]);
                    a1[m][s] = fmaf(xx, w1[m], a1[m][s]);
                }
            }
        }
    }
}

// LayerNorm; g/b in position layout -> one LDS.64 each.
__device__ __forceinline__ void ln_pairp(float r0, float r1,
                                         const float* __restrict__ g, const float* __restrict__ b,
                                         int lane, float& y0, float& y1) {
    float m = warp_sum(r0 + r1) * (1.f / 64.f);
    float d0 = r0 - m, d1 = r1 - m;
    float v = warp_sum(d0 * d0 + d1 * d1) * (1.f / 64.f);
    float inv = rsqrtf(v + EPS_LN);
    const float2 gv = *reinterpret_cast<const float2*>(g + 2 * lane);
    const float2 bv = *reinterpret_cast<const float2*>(b + 2 * lane);
    y0 = d0 * inv * gv.x + bv.x;
    y1 = d1 * inv * gv.y + bv.y;
}

// ---------------------------------------------------------------------------
// zero scratch
// ---------------------------------------------------------------------------
__global__ void zero_kernel() {
    size_t i = (size_t)blockIdx.x * blockDim.x + threadIdx.x;
    size_t stride = (size_t)gridDim.x * blockDim.x;
    float4* p = reinterpret_cast<float4*>(g_acc);
    size_t n4 = (2ull * NA_N * 256ull) / 4;
    for (size_t j = i; j < n4; j += stride) p[j] = make_float4(0.f, 0.f, 0.f, 0.f);
    for (size_t j = i; j < 2 * NA_N; j += stride) g_cnt[j] = 0;
}

// ---------------------------------------------------------------------------
// Fold b_proj into src k/v weights.
// ---------------------------------------------------------------------------
__global__ void fuse_kernel(const float* __restrict__ Wb, const float* __restrict__ bb,
                            const float* __restrict__ Wqkv, const float* __restrict__ bqkv) {
    const int t = blockIdx.x;
    const int tid = threadIdx.x;
    for (int idx = tid; idx < 64 * 128; idx += blockDim.x) {
        int c = idx >> 7, f = idx & 127;
        const float* wq = Wqkv + t * 12288 + (64 + f) * 64;
        const float* wb = Wb + t * 4096;
        float s = 0.f;
#pragma unroll 8
        for (int m = 0; m < 64; m++) s = fmaf(wq[m], wb[m * 64 + c], s);
        g_wfuse[t * 8192 + c * 128 + f] = s;
    }
    if (tid < 128) {
        const float* wq = Wqkv + t * 12288 + (64 + tid) * 64;
        const float* bbp = bb + t * 64;
        float s = bqkv[t * 192 + 64 + tid];
#pragma unroll 8
        for (int m = 0; m < 64; m++) s = fmaf(wq[m], bbp[m], s);
        g_bfuse[t * 128 + tid] = s;
    }
}

// ---------------------------------------------------------------------------
// Precompute per-(type, A-node): q,k,v of the dst tokens. One warp per node.
// ---------------------------------------------------------------------------
__global__ void __launch_bounds__(THREADS_BLK, 1) dstpre_kernel(
    const float* __restrict__ xA,
    const float* __restrict__ Wqkv, const float* __restrict__ bqkv) {
    extern __shared__ float smem[];
    float* sWq = smem;            // [c][192]
    float* sbq = sWq + 12288;     // 192
    float* bufs = sbq + 192;      // WARPS * 256

    const int type = blockIdx.x & 1;
    const int bidx = blockIdx.x >> 1;
    const int tid = threadIdx.x;
    {
        const float* p = Wqkv + type * 12288;
        for (int i = tid; i < 12288; i += THREADS_BLK) { int g = i >> 6, c = i & 63; sWq[c * 192 + g] = p[i]; }
        if (tid < 192) sbq[tid] = bqkv[type * 192 + tid];
    }
    __syncthreads();

    const int warp = tid >> 5, lane = tid & 31;
    float* buf = bufs + warp * 256;
    const int woff3[3] = {0, 64, 128};

    for (int n = bidx * WARPS_PER_BLK + warp; n < NA_N; n += NODE_STRIDE) {
        const float4* gx = reinterpret_cast<const float4*>(xA + (size_t)n * 256);
        reinterpret_cast<float4*>(buf)[lane]      = __ldg(gx + lane);
        reinterpret_cast<float4*>(buf)[lane + 32] = __ldg(gx + lane + 32);
        __syncwarp();
        float a0[3][4], a1[3][4];
        mmqkv_core<3, 192>(buf, sWq, woff3, lane, a0, a1);
        float* outp = g_dstqkv + ((size_t)type * NA_N + n) * 768;
#pragma unroll
        for (int m = 0; m < 3; m++) {
            float b0 = sbq[woff3[m] + lane], b1 = sbq[woff3[m] + lane + 32];
#pragma unroll
            for (int s = 0; s < 4; s++) {
                outp[m * 256 + s * 64 + lane]      = a0[m][s] + b0;
                outp[m * 256 + s * 64 + lane + 32] = a1[m][s] + b1;
            }
        }
        __syncwarp();
    }
}

// ---------------------------------------------------------------------------
// Precompute per-(type, src-node): k,v of projected src tokens, fused weights.
// ---------------------------------------------------------------------------
__global__ void __launch_bounds__(THREADS_BLK, 1) srcpre_kernel(
    const float* __restrict__ xA, const float* __restrict__ xB) {
    extern __shared__ float smem[];
    float* sWf = smem;            // [c][128]
    float* sbf = sWf + 8192;      // 128
    float* bufs = sbf + 128;      // WARPS * 256

    const int type = blockIdx.x & 1;
    const int bidx = blockIdx.x >> 1;
    const int tid = threadIdx.x;
    {
        const float* p = g_wfuse + type * 8192;
        for (int i = tid; i < 8192; i += THREADS_BLK) sWf[i] = p[i];
        if (tid < 128) sbf[tid] = g_bfuse[type * 128 + tid];
    }
    __syncthreads();

    const int warp = tid >> 5, lane = tid & 31;
    float* buf = bufs + warp * 256;
    const float* xsrc = type ? xA : xB;
    const int NSRC = NA_N;
    const int woff2[2] = {0, 64};

    for (int n = bidx * WARPS_PER_BLK + warp; n < NSRC; n += NODE_STRIDE) {
        const float4* gx = reinterpret_cast<const float4*>(xsrc + (size_t)n * 256);
        reinterpret_cast<float4*>(buf)[lane]      = __ldg(gx + lane);
        reinterpret_cast<float4*>(buf)[lane + 32] = __ldg(gx + lane + 32);
        __syncwarp();
        float a0[2][4], a1[2][4];
        mmqkv_core<2, 128>(buf, sWf, woff2, lane, a0, a1);
        float* outp = g_srckv + ((size_t)type * NA_N + n) * 512;
#pragma unroll
        for (int m = 0; m < 2; m++) {
            float b0 = sbf[woff2[m] + lane], b1 = sbf[woff2[m] + lane + 32];
#pragma unroll
            for (int s = 0; s < 4; s++) {
                outp[m * 256 + s * 64 + lane]      = a0[m][s] + b0;
                outp[m * 256 + s * 64 + lane + 32] = a1[m][s] + b1;
            }
        }
        __syncwarp();
    }
}

// ---------------------------------------------------------------------------
// per-edge: TWO edges per warp. Swizzled k/v smem layout
//   float4 unit(t, d, eidx, h) = t*32 + (d>>2)*8 + eidx*4 + h
// makes both the gather stores and the attention float4 reads conflict-free.
// GEMM path uses position-permuted activations/weights (one LDS.64 per weight
// pair). Per-warp smem (2560 floats): qox[512] | kbuf[1024](ffb alias) | vbuf[1024]
// ---------------------------------------------------------------------------
__global__ void __launch_bounds__(THREADS_BLK, 1) edge_kernel(
    const float* __restrict__ xA,
    const int* __restrict__ e0, int E0,
    const int* __restrict__ e1, int E1,
    const float* __restrict__ Wo,  const float* __restrict__ bo,
    const float* __restrict__ g1,  const float* __restrict__ be1,
    const float* __restrict__ W1,  const float* __restrict__ bf1,
    const float* __restrict__ W2,  const float* __restrict__ bf2,
    const float* __restrict__ g2,  const float* __restrict__ be2) {
    extern __shared__ float smem[];
    float* sWo  = smem;              // [pos_c][pos_f]  64*64
    float* sW1  = sWo + 4096;        // [pos_c][pos_f]  64*64
    float* sW2  = sW1 + 4096;        // [pos_f][pos_c]  64*64
    float* sbo  = sW2 + 4096;        // 64 (position layout)
    float* sbf1 = sbo + 64;
    float* sbf2 = sbf1 + 64;
    float* sg1  = sbf2 + 64;
    float* sbe1 = sg1 + 64;
    float* sg2  = sbe1 + 64;
    float* sbe2 = sg2 + 64;
    float* bufs = sbe2 + 64;         // WARPS * 2560

    const int type = blockIdx.x & 1;
    const int bidx = blockIdx.x >> 1;
    const int tid = threadIdx.x;
    {
        const float* p = Wo + type * 4096;
        for (int i = tid; i < 4096; i += THREADS_BLK) { int f = i >> 6, c = i & 63; sWo[posof(c) * 64 + posof(f)] = p[i]; }
        p = W1 + type * 4096;
        for (int i = tid; i < 4096; i += THREADS_BLK) { int f = i >> 6, c = i & 63; sW1[posof(c) * 64 + posof(f)] = p[i]; }
        p = W2 + type * 4096;
        for (int i = tid; i < 4096; i += THREADS_BLK) { int c = i >> 6, f = i & 63; sW2[posof(f) * 64 + posof(c)] = p[i]; }
        if (tid < 64) sbo[posof(tid)]  = bo[type * 64 + tid];
        if (tid < 64) sbf1[posof(tid)] = bf1[type * 64 + tid];
        if (tid < 64) sbf2[posof(tid)] = bf2[type * 64 + tid];
        if (tid < 64) sg1[posof(tid)]  = g1[type * 64 + tid];
        if (tid < 64) sbe1[posof(tid)] = be1[type * 64 + tid];
        if (tid < 64) sg2[posof(tid)]  = g2[type * 64 + tid];
        if (tid < 64) sbe2[posof(tid)] = be2[type * 64 + tid];
        // zero per-warp buffers so an invalid tail edge computes on finite data
        for (int i = tid; i < WARPS_PER_BLK * 2560; i += THREADS_BLK) bufs[i] = 0.f;
    }
    __syncthreads();

    const int warp = tid >> 5, lane = tid & 31;
    const int eidx = lane >> 4, l16 = lane & 15;    // half-warp edge slot
    float* buf  = bufs + warp * 2560;
    float* qox  = buf;            // 512 (position layout, 2 edges)
    float* kbuf = buf + 512;      // 1024 swizzled (ffb aliases after attention)
    float* vbuf = buf + 1536;     // 1024 swizzled
    float* ffb  = kbuf;           // 512 used

    const int* ei = type ? e1 : e0;
    const int  E  = type ? E1 : E0;
    float* accbase = g_acc + (size_t)type * NA_N * 256ull;
    int*   cntbase = g_cnt + type * NA_N;

    for (int e = bidx * (WARPS_PER_BLK * 2) + warp * 2; e < E; e += PAIR_STRIDE) {
        const bool v1 = (e + 1 < E);
        const int s0 = __ldg(ei + e);
        const int d0 = __ldg(ei + E + e);
        const int s1 = v1 ? __ldg(ei + e + 1) : s0;
        const int d1 = v1 ? __ldg(ei + E + e + 1) : d0;
        const int de = eidx ? d1 : d0;
        const int se = eidx ? s1 : s0;
        const float* dq_base = g_dstqkv + ((size_t)type * NA_N + de) * 768;

        // Gather k,v into swizzled layout; conflict-free STS.128
        {
            const float4* gdq = reinterpret_cast<const float4*>(dq_base);
            const float4* gsk = reinterpret_cast<const float4*>(g_srckv + ((size_t)type * NA_N + se) * 512);
            float4* kb4 = reinterpret_cast<float4*>(kbuf);
            float4* vb4 = reinterpret_cast<float4*>(vbuf);
            const int slotu = (l16 & 3) * 8 + eidx * 4 + (l16 >> 2);
#pragma unroll
            for (int j = 0; j < 4; j++) {
                kb4[j * 32 + slotu]       = __ldg(gdq + 64  + l16 + 16 * j);  // dst k row j
                vb4[j * 32 + slotu]       = __ldg(gdq + 128 + l16 + 16 * j);  // dst v row j
                kb4[(4 + j) * 32 + slotu] = __ldg(gsk + l16 + 16 * j);        // src k row 4+j
                vb4[(4 + j) * 32 + slotu] = __ldg(gsk + 64 + l16 + 16 * j);   // src v row 4+j
            }
        }

        // xi residual prefetch into registers: coalesced LDG.32 (channels lane, lane+32)
        float xr0[8], xr1[8];
#pragma unroll
        for (int t = 0; t < 8; t++) {
            const int dd = (t >= 4) ? d1 : d0;
            const float* xp = xA + (size_t)dd * 256 + (t & 3) * 64;
            xr0[t] = __ldg(xp + lane);
            xr1[t] = __ldg(xp + lane + 32);
        }
        __syncwarp();

        // attention: 32 lanes = 2 edges x 4 heads x 4 query tokens.
        {
            const int h = (lane >> 2) & 3, s = lane & 3;
            const float4* qp4 = reinterpret_cast<const float4*>(dq_base + s * 64 + h * 16);
            float4 qa = __ldg(qp4), qb = __ldg(qp4 + 1), qc = __ldg(qp4 + 2), qd = __ldg(qp4 + 3);
            const float* kbase = kbuf + (eidx * 4 + h) * 4;   // + t*128 + q*32
            const float* vbase = vbuf + (eidx * 4 + h) * 4;
            float scr[8];
#pragma unroll
            for (int t = 0; t < 8; t++) {
                const float* kp = kbase + t * 128;
                float4 k0 = *reinterpret_cast<const float4*>(kp);
                float4 k1 = *reinterpret_cast<const float4*>(kp + 32);
                float4 k2 = *reinterpret_cast<const float4*>(kp + 64);
                float4 k3 = *reinterpret_cast<const float4*>(kp + 96);
                float a = qa.x * k0.x;
                a = fmaf(qa.y, k0.y, a); a = fmaf(qa.z, k0.z, a); a = fmaf(qa.w, k0.w, a);
                a = fmaf(qb.x, k1.x, a); a = fmaf(qb.y, k1.y, a); a = fmaf(qb.z, k1.z, a); a = fmaf(qb.w, k1.w, a);
                a = fmaf(qc.x, k2.x, a); a = fmaf(qc.y, k2.y, a); a = fmaf(qc.z, k2.z, a); a = fmaf(qc.w, k2.w, a);
                a = fmaf(qd.x, k3.x, a); a = fmaf(qd.y, k3.y, a); a = fmaf(qd.z, k3.z, a); a = fmaf(qd.w, k3.w, a);
                scr[t] = a * 0.25f;  // 1/sqrt(16)
            }
            float m = scr[0];
#pragma unroll
            for (int t = 1; t < 8; t++) m = fmaxf(m, scr[t]);
            float ssum = 0.f;
#pragma unroll
            for (int t = 0; t < 8; t++) { scr[t] = __expf(scr[t] - m); ssum += scr[t]; }
            float inv = 1.f / ssum;
            float o[16];
#pragma unroll
            for (int d = 0; d < 16; d++) o[d] = 0.f;
#pragma unroll
            for (int t = 0; t < 8; t++) {
                const float* vp = vbase + t * 128;
                float4 v0 = *reinterpret_cast<const float4*>(vp);
                float4 v1_ = *reinterpret_cast<const float4*>(vp + 32);
                float4 v2 = *reinterpret_cast<const float4*>(vp + 64);
                float4 v3 = *reinterpret_cast<const float4*>(vp + 96);
                float p = scr[t] * inv;
                o[0]  = fmaf(p, v0.x, o[0]);  o[1]  = fmaf(p, v0.y, o[1]);
                o[2]  = fmaf(p, v0.z, o[2]);  o[3]  = fmaf(p, v0.w, o[3]);
                o[4]  = fmaf(p, v1_.x, o[4]); o[5]  = fmaf(p, v1_.y, o[5]);
                o[6]  = fmaf(p, v1_.z, o[6]); o[7]  = fmaf(p, v1_.w, o[7]);
                o[8]  = fmaf(p, v2.x, o[8]);  o[9]  = fmaf(p, v2.y, o[9]);
                o[10] = fmaf(p, v2.z, o[10]); o[11] = fmaf(p, v2.w, o[11]);
                o[12] = fmaf(p, v3.x, o[12]); o[13] = fmaf(p, v3.y, o[13]);
                o[14] = fmaf(p, v3.z, o[14]); o[15] = fmaf(p, v3.w, o[15]);
            }
            // store o at permuted positions; rotation makes each step hit 32 banks
            const int pb = (h < 2) ? (2 * h * 16) : (2 * (h - 2) * 16 + 1);
            float* op = qox + eidx * 256 + s * 64;
            const int rot = s + ((h & 1) << 2) + (eidx << 3);
#pragma unroll
            for (int i = 0; i < 16; i++) {
                int d = (i + rot) & 15;
                op[pb + 2 * d] = o[d];
            }
        }
        __syncwarp();

        // attn proj (S=8) + residual(regs) + LN1; rewrites qox (position layout)
        {
            float2 acc[8];
            mm64p_core<8>(qox, 64, sWo, lane, acc);
            __syncwarp();
            const float2 bv = *reinterpret_cast<const float2*>(sbo + 2 * lane);
#pragma unroll
            for (int t = 0; t < 8; t++) {
                float r0 = acc[t].x + bv.x + xr0[t];
                float r1 = acc[t].y + bv.y + xr1[t];
                float y0, y1;
                ln_pairp(r0, r1, sg1, sbe1, lane, y0, y1);
                *reinterpret_cast<float2*>(qox + t * 64 + 2 * lane) = make_float2(y0, y1);
            }
        }
        __syncwarp();

        // FF1 (relu): qox -> ffb (aliases kbuf; k is dead)
        {
            float2 acc[8];
            mm64p_core<8>(qox, 64, sW1, lane, acc);
            const float2 bv = *reinterpret_cast<const float2*>(sbf1 + 2 * lane);
#pragma unroll
            for (int s = 0; s < 8; s++) {
                float r0 = fmaxf(acc[s].x + bv.x, 0.f);
                float r1 = fmaxf(acc[s].y + bv.y, 0.f);
                *reinterpret_cast<float2*>(ffb + s * 64 + 2 * lane) = make_float2(r0, r1);
            }
        }
        __syncwarp();

        // FF2 + residual(qox) + LN2 -> vector atomic scatter (position layout)
        {
            float2 acc[8];
            mm64p_core<8>(ffb, 64, sW2, lane, acc);
            const float2 bv = *reinterpret_cast<const float2*>(sbf2 + 2 * lane);
#pragma unroll
            for (int t = 0; t < 8; t++) {
                if (t < 4 || v1) {
                    const int dd = (t >= 4) ? d1 : d0;
                    float* accp = accbase + (size_t)dd * 256 + (t & 3) * 64;
                    const float2 xv = *reinterpret_cast<const float2*>(qox + t * 64 + 2 * lane);
                    float r0 = acc[t].x + bv.x + xv.x;
                    float r1 = acc[t].y + bv.y + xv.y;
                    float y0, y1;
                    ln_pairp(r0, r1, sg2, sbe2, lane, y0, y1);
                    asm volatile("red.global.add.v2.f32 [%0], {%1, %2};"
                                 :: "l"(accp + 2 * lane), "f"(y0), "f"(y1) : "memory");
                }
            }
            if (lane == 0) {
                atomicAdd(cntbase + d0, 1);
                if (v1) atomicAdd(cntbase + d1, 1);
            }
        }
        __syncwarp();
    }
}

// ---------------------------------------------------------------------------
// final: mean across edge types (un-permuting position layout), Wout per token,
// sum over tokens, softmax(32). One warp per node.
// ---------------------------------------------------------------------------
__global__ void __launch_bounds__(128) out_kernel(const float* __restrict__ Wout,
                                                  const float* __restrict__ bout,
                                                  float* __restrict__ out) {
    __shared__ float sW[2048];   // [c][o]
    __shared__ float sb[32];
    __shared__ float comb[4][256];
    const int tid = threadIdx.x;
    for (int i = tid; i < 2048; i += 128) { int o = i >> 6, c = i & 63; sW[c * 32 + o] = Wout[i]; }
    if (tid < 32) sb[tid] = bout[tid];
    __syncthreads();

    const int warp = tid >> 5, lane = tid & 31;
    const int n = blockIdx.x * 4 + warp;
    if (n >= NA_N) return;

    const int c0 = g_cnt[n], c1 = g_cnt[NA_N + n];
    const float i0 = (c0 > 0) ? 0.5f / (float)c0 : 0.f;
    const float i1 = (c1 > 0) ? 0.5f / (float)c1 : 0.f;
    const float* a0 = g_acc + (size_t)n * 256;
    const float* a1 = g_acc + (size_t)NA_N * 256 + (size_t)n * 256;
    float* cb = comb[warp];
#pragma unroll
    for (int j = 0; j < 8; j++) {
        int i = lane + 32 * j;
        int t = i >> 6, p = i & 63;
        int c = ((p & 1) << 5) + (p >> 1);   // channel of position p
        cb[t * 64 + c] = a0[i] * i0 + a1[i] * i1;
    }
    __syncwarp();

    float h = 0.f;
#pragma unroll 4
    for (int i = 0; i < 256; i++) {
        int c = i & 63;
        h = fmaf(cb[i], sW[c * 32 + lane], h);
    }
    h += 4.f * sb[lane];

    float m = warp_max(h);
    float ex = __expf(h - m);
    float s = warp_sum(ex);
    out[(size_t)n * 32 + lane] = ex / s;
}

// ---------------------------------------------------------------------------
extern "C" void kernel_launch(void* const* d_in, const int* in_sizes, int n_in,
                              void* d_out, int out_size) {
    const float* xA   = (const float*)d_in[0];
    const float* xB   = (const float*)d_in[1];
    const int*   e0   = (const int*)d_in[2];
    const int*   e1   = (const int*)d_in[3];
    const float* Wb   = (const float*)d_in[4];
    const float* bb   = (const float*)d_in[5];
    const float* Wqkv = (const float*)d_in[6];
    const float* bqkv = (const float*)d_in[7];
    const float* Wo   = (const float*)d_in[8];
    const float* bo   = (const float*)d_in[9];
    const float* g1   = (const float*)d_in[10];
    const float* be1  = (const float*)d_in[11];
    const float* W1   = (const float*)d_in[12];
    const float* bf1  = (const float*)d_in[13];
    const float* W2   = (const float*)d_in[14];
    const float* bf2  = (const float*)d_in[15];
    const float* g2   = (const float*)d_in[16];
    const float* be2  = (const float*)d_in[17];
    const float* Wout = (const float*)d_in[18];
    const float* bout = (const float*)d_in[19];

    const int E0 = in_sizes[2] / 2;
    const int E1 = in_sizes[3] / 2;

    const int dst_smem  = (12288 + 192 + WARPS_PER_BLK * 256) * 4;
    const int src_smem  = (8192 + 128 + WARPS_PER_BLK * 256) * 4;
    const int edge_smem = (3 * 4096 + 7 * 64 + WARPS_PER_BLK * 2560) * 4;   // 173,824 B
    cudaFuncSetAttribute(dstpre_kernel, cudaFuncAttributeMaxDynamicSharedMemorySize, dst_smem);
    cudaFuncSetAttribute(srcpre_kernel, cudaFuncAttributeMaxDynamicSharedMemorySize, src_smem);
    cudaFuncSetAttribute(edge_kernel,   cudaFuncAttributeMaxDynamicSharedMemorySize, edge_smem);

    zero_kernel<<<2048, 256>>>();
    fuse_kernel<<<2, 256>>>(Wb, bb, Wqkv, bqkv);
    dstpre_kernel<<<2 * 148, THREADS_BLK, dst_smem>>>(xA, Wqkv, bqkv);
    srcpre_kernel<<<2 * 148, THREADS_BLK, src_smem>>>(xA, xB);
    edge_kernel<<<2 * EDGE_BLOCKS, THREADS_BLK, edge_smem>>>(
        xA, e0, E0, e1, E1,
        Wo, bo, g1, be1, W1, bf1, W2, bf2, g2, be2);
    out_kernel<<<(NA_N + 3) / 4, 128>>>(Wout, bout, (float*)d_out);
}

// round 11
// speedup vs baseline: 1.0841x; 1.0841x over previous
#include <cuda_runtime.h>
#include <math.h>
#include <stdint.h>

// Problem constants (fixed-shape problem)
#define NA_N   40000
#define NB_N   40000
#define EPS_LN 1e-5f

#define WARPS_PER_BLK 12
#define EDGE_BLOCKS   148          // per edge type
#define THREADS_BLK   (WARPS_PER_BLK * 32)
#define PAIR_STRIDE   (EDGE_BLOCKS * WARPS_PER_BLK * 2)
#define NODE_STRIDE   (148 * WARPS_PER_BLK)

// Scratch (static device arrays; no runtime alloc)
__device__ float g_acc[2ull * NA_N * 256ull];
__device__ int   g_cnt[2 * NA_N];
// Precomputed per-(type,node) projections:
//   g_dstqkv[t][n][0:256)=q, [256:512)=k, [512:768)=v   (from xA, Wqkv[t])
//   g_srckv [t][n][0:256)=k, [256:512)=v                (fused (Wk·Wb)x form)
__device__ float g_dstqkv[2ull * NA_N * 768ull];
__device__ float g_srckv [2ull * NA_N * 512ull];
// Fused src weights: [t][c][128] (k|v feature columns), biases [t][128]
__device__ float g_wfuse[2 * 64 * 128];
__device__ float g_bfuse[2 * 128];

// ---------------------------------------------------------------------------
// helpers
// ---------------------------------------------------------------------------
__device__ __forceinline__ float warp_sum(float v) {
#pragma unroll
    for (int o = 16; o; o >>= 1) v += __shfl_xor_sync(0xffffffffu, v, o);
    return v;
}
__device__ __forceinline__ float warp_max(float v) {
#pragma unroll
    for (int o = 16; o; o >>= 1) v = fmaxf(v, __shfl_xor_sync(0xffffffffu, v, o));
    return v;
}

// Single-matrix GEMM core: out[s][f] partials over 64-dim reduction.
// Weights [c][f] in smem, lane owns (lane, lane+32) -> two LDS.32, conflict-free.
// Input rows read as broadcast float4 LDS.
template <int S>
__device__ __forceinline__ void mm64_core(const float* __restrict__ in, int in_stride,
                                          const float* __restrict__ Wt, int wstride,
                                          int lane, float* a0, float* a1) {
#pragma unroll
    for (int s = 0; s < S; s++) { a0[s] = 0.f; a1[s] = 0.f; }
#pragma unroll
    for (int c4 = 0; c4 < 16; c4++) {
        float4 xv[S];
#pragma unroll
        for (int s = 0; s < S; s++)
            xv[s] = *reinterpret_cast<const float4*>(in + s * in_stride + (c4 << 2));
#pragma unroll
        for (int j = 0; j < 4; j++) {
            const float* wrow = Wt + ((c4 << 2) + j) * wstride;
            float w0 = wrow[lane];
            float w1 = wrow[lane + 32];
#pragma unroll
            for (int s = 0; s < S; s++) {
                float xx = (j == 0) ? xv[s].x : (j == 1) ? xv[s].y : (j == 2) ? xv[s].z : xv[s].w;
                a0[s] = fmaf(xx, w0, a0[s]);
                a1[s] = fmaf(xx, w1, a1[s]);
            }
        }
    }
}

template <int S, bool RELU>
__device__ __forceinline__ void mm64_store(const float* __restrict__ in, int in_stride,
                                           const float* __restrict__ Wt, int wstride,
                                           const float* __restrict__ bias,
                                           float* __restrict__ out, int out_stride, int lane) {
    float a0[S], a1[S];
    mm64_core<S>(in, in_stride, Wt, wstride, lane, a0, a1);
    float b0 = bias[lane], b1 = bias[lane + 32];
#pragma unroll
    for (int s = 0; s < S; s++) {
        float r0 = a0[s] + b0, r1 = a1[s] + b1;
        if (RELU) { r0 = fmaxf(r0, 0.f); r1 = fmaxf(r1, 0.f); }
        out[s * out_stride + lane]      = r0;
        out[s * out_stride + lane + 32] = r1;
    }
}

// Fused multi-matrix sweep over W ([c][WSTRIDE] layout): M weight streams.
template <int M, int WSTRIDE>
__device__ __forceinline__ void mmqkv_core(const float* __restrict__ in,
                                           const float* __restrict__ Wq, const int* woff,
                                           int lane, float (*a0)[4], float (*a1)[4]) {
#pragma unroll
    for (int m = 0; m < M; m++)
#pragma unroll
        for (int s = 0; s < 4; s++) { a0[m][s] = 0.f; a1[m][s] = 0.f; }
#pragma unroll
    for (int c4 = 0; c4 < 16; c4++) {
        float4 xv[4];
#pragma unroll
        for (int s = 0; s < 4; s++)
            xv[s] = *reinterpret_cast<const float4*>(in + s * 64 + (c4 << 2));
#pragma unroll
        for (int j = 0; j < 4; j++) {
            const float* wrow = Wq + ((c4 << 2) + j) * WSTRIDE;
            float w0[M], w1[M];
#pragma unroll
            for (int m = 0; m < M; m++) {
                w0[m] = wrow[woff[m] + lane];
                w1[m] = wrow[woff[m] + lane + 32];
            }
#pragma unroll
            for (int s = 0; s < 4; s++) {
                float xx = (j == 0) ? xv[s].x : (j == 1) ? xv[s].y : (j == 2) ? xv[s].z : xv[s].w;
#pragma unroll
                for (int m = 0; m < M; m++) {
                    a0[m][s] = fmaf(xx, w0[m], a0[m][s]);
                    a1[m][s] = fmaf(xx, w1[m], a1[m][s]);
                }
            }
        }
    }
}

// LayerNorm over 64 features distributed as (lane, lane+32).
__device__ __forceinline__ void ln_pair(float r0, float r1,
                                        const float* __restrict__ g, const float* __restrict__ b,
                                        int lane, float& y0, float& y1) {
    float m = warp_sum(r0 + r1) * (1.f / 64.f);
    float d0 = r0 - m, d1 = r1 - m;
    float v = warp_sum(d0 * d0 + d1 * d1) * (1.f / 64.f);
    float inv = rsqrtf(v + EPS_LN);
    y0 = d0 * inv * g[lane]      + b[lane];
    y1 = d1 * inv * g[lane + 32] + b[lane + 32];
}

// ---------------------------------------------------------------------------
// zero scratch
// ---------------------------------------------------------------------------
__global__ void zero_kernel() {
    size_t i = (size_t)blockIdx.x * blockDim.x + threadIdx.x;
    size_t stride = (size_t)gridDim.x * blockDim.x;
    float4* p = reinterpret_cast<float4*>(g_acc);
    size_t n4 = (2ull * NA_N * 256ull) / 4;
    for (size_t j = i; j < n4; j += stride) p[j] = make_float4(0.f, 0.f, 0.f, 0.f);
    for (size_t j = i; j < 2 * NA_N; j += stride) g_cnt[j] = 0;
}

// ---------------------------------------------------------------------------
// Fold b_proj into src k/v weights.
// ---------------------------------------------------------------------------
__global__ void fuse_kernel(const float* __restrict__ Wb, const float* __restrict__ bb,
                            const float* __restrict__ Wqkv, const float* __restrict__ bqkv) {
    const int t = blockIdx.x;
    const int tid = threadIdx.x;
    for (int idx = tid; idx < 64 * 128; idx += blockDim.x) {
        int c = idx >> 7, f = idx & 127;
        const float* wq = Wqkv + t * 12288 + (64 + f) * 64;
        const float* wb = Wb + t * 4096;
        float s = 0.f;
#pragma unroll 8
        for (int m = 0; m < 64; m++) s = fmaf(wq[m], wb[m * 64 + c], s);
        g_wfuse[t * 8192 + c * 128 + f] = s;
    }
    if (tid < 128) {
        const float* wq = Wqkv + t * 12288 + (64 + tid) * 64;
        const float* bbp = bb + t * 64;
        float s = bqkv[t * 192 + 64 + tid];
#pragma unroll 8
        for (int m = 0; m < 64; m++) s = fmaf(wq[m], bbp[m], s);
        g_bfuse[t * 128 + tid] = s;
    }
}

// ---------------------------------------------------------------------------
// Precompute per-(type, A-node): q,k,v of the dst tokens. One warp per node.
// ---------------------------------------------------------------------------
__global__ void __launch_bounds__(THREADS_BLK, 1) dstpre_kernel(
    const float* __restrict__ xA,
    const float* __restrict__ Wqkv, const float* __restrict__ bqkv) {
    extern __shared__ float smem[];
    float* sWq = smem;            // [c][192]
    float* sbq = sWq + 12288;     // 192
    float* bufs = sbq + 192;      // WARPS * 256

    const int type = blockIdx.x & 1;
    const int bidx = blockIdx.x >> 1;
    const int tid = threadIdx.x;
    {
        const float* p = Wqkv + type * 12288;
        for (int i = tid; i < 12288; i += THREADS_BLK) { int g = i >> 6, c = i & 63; sWq[c * 192 + g] = p[i]; }
        if (tid < 192) sbq[tid] = bqkv[type * 192 + tid];
    }
    __syncthreads();

    const int warp = tid >> 5, lane = tid & 31;
    float* buf = bufs + warp * 256;
    const int woff3[3] = {0, 64, 128};

    for (int n = bidx * WARPS_PER_BLK + warp; n < NA_N; n += NODE_STRIDE) {
        const float4* gx = reinterpret_cast<const float4*>(xA + (size_t)n * 256);
        reinterpret_cast<float4*>(buf)[lane]      = __ldg(gx + lane);
        reinterpret_cast<float4*>(buf)[lane + 32] = __ldg(gx + lane + 32);
        __syncwarp();
        float a0[3][4], a1[3][4];
        mmqkv_core<3, 192>(buf, sWq, woff3, lane, a0, a1);
        float* outp = g_dstqkv + ((size_t)type * NA_N + n) * 768;
#pragma unroll
        for (int m = 0; m < 3; m++) {
            float b0 = sbq[woff3[m] + lane], b1 = sbq[woff3[m] + lane + 32];
#pragma unroll
            for (int s = 0; s < 4; s++) {
                outp[m * 256 + s * 64 + lane]      = a0[m][s] + b0;
                outp[m * 256 + s * 64 + lane + 32] = a1[m][s] + b1;
            }
        }
        __syncwarp();
    }
}

// ---------------------------------------------------------------------------
// Precompute per-(type, src-node): k,v of projected src tokens, fused weights.
// ---------------------------------------------------------------------------
__global__ void __launch_bounds__(THREADS_BLK, 1) srcpre_kernel(
    const float* __restrict__ xA, const float* __restrict__ xB) {
    extern __shared__ float smem[];
    float* sWf = smem;            // [c][128]
    float* sbf = sWf + 8192;      // 128
    float* bufs = sbf + 128;      // WARPS * 256

    const int type = blockIdx.x & 1;
    const int bidx = blockIdx.x >> 1;
    const int tid = threadIdx.x;
    {
        const float* p = g_wfuse + type * 8192;
        for (int i = tid; i < 8192; i += THREADS_BLK) sWf[i] = p[i];
        if (tid < 128) sbf[tid] = g_bfuse[type * 128 + tid];
    }
    __syncthreads();

    const int warp = tid >> 5, lane = tid & 31;
    float* buf = bufs + warp * 256;
    const float* xsrc = type ? xA : xB;
    const int NSRC = NA_N;
    const int woff2[2] = {0, 64};

    for (int n = bidx * WARPS_PER_BLK + warp; n < NSRC; n += NODE_STRIDE) {
        const float4* gx = reinterpret_cast<const float4*>(xsrc + (size_t)n * 256);
        reinterpret_cast<float4*>(buf)[lane]      = __ldg(gx + lane);
        reinterpret_cast<float4*>(buf)[lane + 32] = __ldg(gx + lane + 32);
        __syncwarp();
        float a0[2][4], a1[2][4];
        mmqkv_core<2, 128>(buf, sWf, woff2, lane, a0, a1);
        float* outp = g_srckv + ((size_t)type * NA_N + n) * 512;
#pragma unroll
        for (int m = 0; m < 2; m++) {
            float b0 = sbf[woff2[m] + lane], b1 = sbf[woff2[m] + lane + 32];
#pragma unroll
            for (int s = 0; s < 4; s++) {
                outp[m * 256 + s * 64 + lane]      = a0[m][s] + b0;
                outp[m * 256 + s * 64 + lane + 32] = a1[m][s] + b1;
            }
        }
        __syncwarp();
    }
}

// ---------------------------------------------------------------------------
// per-edge: TWO edges per warp (R8 structure). ONLY change vs R8: k/v smem uses
// the swizzled layout  unit(t, q, eidx, h) = t*32 + q*8 + eidx*4 + h
// so gather stores stay conflict-free AND attention k/v reads become
// conflict-free LDS.128 (was: 4-way-conflicted scalar LDS).
// Per-warp smem (2560 floats): qox[512] | kbuf[1024](ffb alias) | vbuf[1024]
// ---------------------------------------------------------------------------
__global__ void __launch_bounds__(THREADS_BLK, 1) edge_kernel(
    const float* __restrict__ xA,
    const int* __restrict__ e0, int E0,
    const int* __restrict__ e1, int E1,
    const float* __restrict__ Wo,  const float* __restrict__ bo,
    const float* __restrict__ g1,  const float* __restrict__ be1,
    const float* __restrict__ W1,  const float* __restrict__ bf1,
    const float* __restrict__ W2,  const float* __restrict__ bf2,
    const float* __restrict__ g2,  const float* __restrict__ be2) {
    extern __shared__ float smem[];
    float* sWo  = smem;              // [c][f]  64*64
    float* sW1  = sWo + 4096;        // [c][f]  64*64
    float* sW2  = sW1 + 4096;        // [f][c]  64*64
    float* sbo  = sW2 + 4096;        // 64
    float* sbf1 = sbo + 64;
    float* sbf2 = sbf1 + 64;
    float* sg1  = sbf2 + 64;
    float* sbe1 = sg1 + 64;
    float* sg2  = sbe1 + 64;
    float* sbe2 = sg2 + 64;
    float* bufs = sbe2 + 64;         // WARPS * 2560

    const int type = blockIdx.x & 1;
    const int bidx = blockIdx.x >> 1;
    const int tid = threadIdx.x;
    {
        const float* p = Wo + type * 4096;
        for (int i = tid; i < 4096; i += THREADS_BLK) { int f = i >> 6, c = i & 63; sWo[c * 64 + f] = p[i]; }
        p = W1 + type * 4096;
        for (int i = tid; i < 4096; i += THREADS_BLK) { int f = i >> 6, c = i & 63; sW1[c * 64 + f] = p[i]; }
        p = W2 + type * 4096;
        for (int i = tid; i < 4096; i += THREADS_BLK) { int c = i >> 6, f = i & 63; sW2[f * 64 + c] = p[i]; }
        if (tid < 64) sbo[tid]  = bo[type * 64 + tid];
        if (tid < 64) sbf1[tid] = bf1[type * 64 + tid];
        if (tid < 64) sbf2[tid] = bf2[type * 64 + tid];
        if (tid < 64) sg1[tid]  = g1[type * 64 + tid];
        if (tid < 64) sbe1[tid] = be1[type * 64 + tid];
        if (tid < 64) sg2[tid]  = g2[type * 64 + tid];
        if (tid < 64) sbe2[tid] = be2[type * 64 + tid];
        // zero per-warp buffers so an invalid tail edge computes on finite data
        for (int i = tid; i < WARPS_PER_BLK * 2560; i += THREADS_BLK) bufs[i] = 0.f;
    }
    __syncthreads();

    const int warp = tid >> 5, lane = tid & 31;
    const int eidx = lane >> 4, l16 = lane & 15;    // half-warp edge slot
    float* buf  = bufs + warp * 2560;
    float* qox  = buf;            // 512 (canonical layout, 2 edges)
    float* kbuf = buf + 512;      // 1024 swizzled (ffb aliases after attention)
    float* vbuf = buf + 1536;     // 1024 swizzled
    float* ffb  = kbuf;           // 512 used

    const int* ei = type ? e1 : e0;
    const int  E  = type ? E1 : E0;
    float* accbase = g_acc + (size_t)type * NA_N * 256ull;
    int*   cntbase = g_cnt + type * NA_N;

    for (int e = bidx * (WARPS_PER_BLK * 2) + warp * 2; e < E; e += PAIR_STRIDE) {
        const bool v1 = (e + 1 < E);
        const int s0 = __ldg(ei + e);
        const int d0 = __ldg(ei + E + e);
        const int s1 = v1 ? __ldg(ei + e + 1) : s0;
        const int d1 = v1 ? __ldg(ei + E + e + 1) : d0;
        const int de = eidx ? d1 : d0;
        const int se = eidx ? s1 : s0;
        const float* dq_base = g_dstqkv + ((size_t)type * NA_N + de) * 768;

        // Gather k,v into swizzled layout; conflict-free STS.128.
        // float4 #l16 of a 64-float row = channels [4*l16,4*l16+4) = (h=l16>>2, q=l16&3)
        {
            const float4* gdq = reinterpret_cast<const float4*>(dq_base);
            const float4* gsk = reinterpret_cast<const float4*>(g_srckv + ((size_t)type * NA_N + se) * 512);
            float4* kb4 = reinterpret_cast<float4*>(kbuf);
            float4* vb4 = reinterpret_cast<float4*>(vbuf);
            const int slotu = (l16 & 3) * 8 + eidx * 4 + (l16 >> 2);
#pragma unroll
            for (int j = 0; j < 4; j++) {
                kb4[j * 32 + slotu]       = __ldg(gdq + 64  + l16 + 16 * j);  // dst k row j
                vb4[j * 32 + slotu]       = __ldg(gdq + 128 + l16 + 16 * j);  // dst v row j
                kb4[(4 + j) * 32 + slotu] = __ldg(gsk + l16 + 16 * j);        // src k row 4+j
                vb4[(4 + j) * 32 + slotu] = __ldg(gsk + 64 + l16 + 16 * j);   // src v row 4+j
            }
        }

        // xi residual prefetch into registers: coalesced LDG.32
        float xr0[8], xr1[8];
#pragma unroll
        for (int t = 0; t < 8; t++) {
            const int dd = (t >= 4) ? d1 : d0;
            const float* xp = xA + (size_t)dd * 256 + (t & 3) * 64;
            xr0[t] = __ldg(xp + lane);
            xr1[t] = __ldg(xp + lane + 32);
        }
        __syncwarp();

        // attention: 32 lanes = 2 edges x 4 heads x 4 query tokens.
        // q straight from global; k/v via conflict-free float4 reads; o stored
        // with STATIC indexing (R8 semantics).
        {
            const int h = (lane >> 2) & 3, s = lane & 3;
            const float4* qp4 = reinterpret_cast<const float4*>(dq_base + s * 64 + h * 16);
            float4 qa = __ldg(qp4), qb = __ldg(qp4 + 1), qc = __ldg(qp4 + 2), qd = __ldg(qp4 + 3);
            const float* kbase = kbuf + (eidx * 4 + h) * 4;   // + t*128 + q*32
            const float* vbase = vbuf + (eidx * 4 + h) * 4;
            float scr[8];
#pragma unroll
            for (int t = 0; t < 8; t++) {
                const float* kp = kbase + t * 128;
                float4 k0 = *reinterpret_cast<const float4*>(kp);
                float4 k1 = *reinterpret_cast<const float4*>(kp + 32);
                float4 k2 = *reinterpret_cast<const float4*>(kp + 64);
                float4 k3 = *reinterpret_cast<const float4*>(kp + 96);
                float a = qa.x * k0.x;
                a = fmaf(qa.y, k0.y, a); a = fmaf(qa.z, k0.z, a); a = fmaf(qa.w, k0.w, a);
                a = fmaf(qb.x, k1.x, a); a = fmaf(qb.y, k1.y, a); a = fmaf(qb.z, k1.z, a); a = fmaf(qb.w, k1.w, a);
                a = fmaf(qc.x, k2.x, a); a = fmaf(qc.y, k2.y, a); a = fmaf(qc.z, k2.z, a); a = fmaf(qc.w, k2.w, a);
                a = fmaf(qd.x, k3.x, a); a = fmaf(qd.y, k3.y, a); a = fmaf(qd.z, k3.z, a); a = fmaf(qd.w, k3.w, a);
                scr[t] = a * 0.25f;  // 1/sqrt(16)
            }
            float m = scr[0];
#pragma unroll
            for (int t = 1; t < 8; t++) m = fmaxf(m, scr[t]);
            float ssum = 0.f;
#pragma unroll
            for (int t = 0; t < 8; t++) { scr[t] = __expf(scr[t] - m); ssum += scr[t]; }
            float inv = 1.f / ssum;
            float o[16];
#pragma unroll
            for (int d = 0; d < 16; d++) o[d] = 0.f;
#pragma unroll
            for (int t = 0; t < 8; t++) {
                const float* vp = vbase + t * 128;
                float4 v0 = *reinterpret_cast<const float4*>(vp);
                float4 vv1 = *reinterpret_cast<const float4*>(vp + 32);
                float4 v2 = *reinterpret_cast<const float4*>(vp + 64);
                float4 v3 = *reinterpret_cast<const float4*>(vp + 96);
                float p = scr[t] * inv;
                o[0]  = fmaf(p, v0.x, o[0]);  o[1]  = fmaf(p, v0.y, o[1]);
                o[2]  = fmaf(p, v0.z, o[2]);  o[3]  = fmaf(p, v0.w, o[3]);
                o[4]  = fmaf(p, vv1.x, o[4]); o[5]  = fmaf(p, vv1.y, o[5]);
                o[6]  = fmaf(p, vv1.z, o[6]); o[7]  = fmaf(p, vv1.w, o[7]);
                o[8]  = fmaf(p, v2.x, o[8]);  o[9]  = fmaf(p, v2.y, o[9]);
                o[10] = fmaf(p, v2.z, o[10]); o[11] = fmaf(p, v2.w, o[11]);
                o[12] = fmaf(p, v3.x, o[12]); o[13] = fmaf(p, v3.y, o[13]);
                o[14] = fmaf(p, v3.z, o[14]); o[15] = fmaf(p, v3.w, o[15]);
            }
            float* op = qox + eidx * 256 + s * 64 + h * 16;
#pragma unroll
            for (int d = 0; d < 16; d++) op[d] = o[d];
        }
        __syncwarp();

        // attn proj (S=8, both edges) + residual(regs) + LN1; rewrites qox
        {
            float a0[8], a1[8];
            mm64_core<8>(qox, 64, sWo, 64, lane, a0, a1);
            __syncwarp();
            float b0 = sbo[lane], b1 = sbo[lane + 32];
#pragma unroll
            for (int t = 0; t < 8; t++) {
                float r0 = a0[t] + b0 + xr0[t];
                float r1 = a1[t] + b1 + xr1[t];
                float y0, y1;
                ln_pair(r0, r1, sg1, sbe1, lane, y0, y1);
                qox[t * 64 + lane]      = y0;
                qox[t * 64 + lane + 32] = y1;
            }
        }
        __syncwarp();

        // FF1 (relu): qox -> ffb (aliases kbuf; k is dead)
        mm64_store<8, true>(qox, 64, sW1, 64, sbf1, ffb, 64, lane);
        __syncwarp();

        // FF2 + residual(qox) + LN2 -> atomic scatter (guard invalid tail edge)
        {
            float a0[8], a1[8];
            mm64_core<8>(ffb, 64, sW2, 64, lane, a0, a1);
            float b0 = sbf2[lane], b1 = sbf2[lane + 32];
#pragma unroll
            for (int t = 0; t < 8; t++) {
                if (t < 4 || v1) {
                    const int dd = (t >= 4) ? d1 : d0;
                    float* accp = accbase + (size_t)dd * 256 + (t & 3) * 64;
                    float r0 = a0[t] + b0 + qox[t * 64 + lane];
                    float r1 = a1[t] + b1 + qox[t * 64 + lane + 32];
                    float y0, y1;
                    ln_pair(r0, r1, sg2, sbe2, lane, y0, y1);
                    atomicAdd(accp + lane, y0);
                    atomicAdd(accp + lane + 32, y1);
                }
            }
            if (lane == 0) {
                atomicAdd(cntbase + d0, 1);
                if (v1) atomicAdd(cntbase + d1, 1);
            }
        }
        __syncwarp();
    }
}

// ---------------------------------------------------------------------------
// final: mean across edge types, Wout per token, sum over tokens, softmax(32)
// one warp per node, 4 nodes per block
// ---------------------------------------------------------------------------
__global__ void __launch_bounds__(128) out_kernel(const float* __restrict__ Wout,
                                                  const float* __restrict__ bout,
                                                  float* __restrict__ out) {
    __shared__ float sW[2048];   // [c][o]
    __shared__ float sb[32];
    __shared__ float comb[4][256];
    const int tid = threadIdx.x;
    for (int i = tid; i < 2048; i += 128) { int o = i >> 6, c = i & 63; sW[c * 32 + o] = Wout[i]; }
    if (tid < 32) sb[tid] = bout[tid];
    __syncthreads();

    const int warp = tid >> 5, lane = tid & 31;
    const int n = blockIdx.x * 4 + warp;
    if (n >= NA_N) return;

    const int c0 = g_cnt[n], c1 = g_cnt[NA_N + n];
    const float i0 = (c0 > 0) ? 0.5f / (float)c0 : 0.f;
    const float i1 = (c1 > 0) ? 0.5f / (float)c1 : 0.f;
    const float* a0 = g_acc + (size_t)n * 256;
    const float* a1 = g_acc + (size_t)NA_N * 256 + (size_t)n * 256;
    float* cb = comb[warp];
#pragma unroll
    for (int j = 0; j < 8; j++) {
        int i = lane + 32 * j;
        cb[i] = a0[i] * i0 + a1[i] * i1;
    }
    __syncwarp();

    float h = 0.f;
#pragma unroll 4
    for (int i = 0; i < 256; i++) {
        int c = i & 63;
        h = fmaf(cb[i], sW[c * 32 + lane], h);
    }
    h += 4.f * sb[lane];

    float m = warp_max(h);
    float ex = __expf(h - m);
    float s = warp_sum(ex);
    out[(size_t)n * 32 + lane] = ex / s;
}

// ---------------------------------------------------------------------------
extern "C" void kernel_launch(void* const* d_in, const int* in_sizes, int n_in,
                              void* d_out, int out_size) {
    const float* xA   = (const float*)d_in[0];
    const float* xB   = (const float*)d_in[1];
    const int*   e0   = (const int*)d_in[2];
    const int*   e1   = (const int*)d_in[3];
    const float* Wb   = (const float*)d_in[4];
    const float* bb   = (const float*)d_in[5];
    const float* Wqkv = (const float*)d_in[6];
    const float* bqkv = (const float*)d_in[7];
    const float* Wo   = (const float*)d_in[8];
    const float* bo   = (const float*)d_in[9];
    const float* g1   = (const float*)d_in[10];
    const float* be1  = (const float*)d_in[11];
    const float* W1   = (const float*)d_in[12];
    const float* bf1  = (const float*)d_in[13];
    const float* W2   = (const float*)d_in[14];
    const float* bf2  = (const float*)d_in[15];
    const float* g2   = (const float*)d_in[16];
    const float* be2  = (const float*)d_in[17];
    const float* Wout = (const float*)d_in[18];
    const float* bout = (const float*)d_in[19];

    const int E0 = in_sizes[2] / 2;
    const int E1 = in_sizes[3] / 2;

    const int dst_smem  = (12288 + 192 + WARPS_PER_BLK * 256) * 4;
    const int src_smem  = (8192 + 128 + WARPS_PER_BLK * 256) * 4;
    const int edge_smem = (3 * 4096 + 7 * 64 + WARPS_PER_BLK * 2560) * 4;   // 173,824 B
    cudaFuncSetAttribute(dstpre_kernel, cudaFuncAttributeMaxDynamicSharedMemorySize, dst_smem);
    cudaFuncSetAttribute(srcpre_kernel, cudaFuncAttributeMaxDynamicSharedMemorySize, src_smem);
    cudaFuncSetAttribute(edge_kernel,   cudaFuncAttributeMaxDynamicSharedMemorySize, edge_smem);

    zero_kernel<<<2048, 256>>>();
    fuse_kernel<<<2, 256>>>(Wb, bb, Wqkv, bqkv);
    dstpre_kernel<<<2 * 148, THREADS_BLK, dst_smem>>>(xA, Wqkv, bqkv);
    srcpre_kernel<<<2 * 148, THREADS_BLK, src_smem>>>(xA, xB);
    edge_kernel<<<2 * EDGE_BLOCKS, THREADS_BLK, edge_smem>>>(
        xA, e0, E0, e1, E1,
        Wo, bo, g1, be1, W1, bf1, W2, bf2, g2, be2);
    out_kernel<<<(NA_N + 3) / 4, 128>>>(Wout, bout, (float*)d_out);
}

// round 12
// speedup vs baseline: 1.1202x; 1.0333x over previous
#include <cuda_runtime.h>
#include <math.h>
#include <stdint.h>

// Problem constants (fixed-shape problem)
#define NA_N   40000
#define NB_N   40000
#define EPS_LN 1e-5f

#define WARPS_PER_BLK 12
#define EDGE_BLOCKS   148          // per edge type
#define THREADS_BLK   (WARPS_PER_BLK * 32)
#define PAIR_STRIDE   (EDGE_BLOCKS * WARPS_PER_BLK * 2)
#define NODE_STRIDE   (148 * WARPS_PER_BLK)

// Scratch (static device arrays; no runtime alloc)
__device__ float g_acc[2ull * NA_N * 256ull];
__device__ int   g_cnt[2 * NA_N];
// Precomputed per-(type,node) projections (canonical channel order):
//   g_dstqkv[t][n][0:256)=q, [256:512)=k, [512:768)=v   (from xA, Wqkv[t])
//   g_srckv [t][n][0:256)=k, [256:512)=v                (fused (Wk·Wb)x form)
__device__ float g_dstqkv[2ull * NA_N * 768ull];
__device__ float g_srckv [2ull * NA_N * 512ull];
// Fused src weights: [t][c][128] (k|v feature columns), biases [t][128]
__device__ float g_wfuse[2 * 64 * 128];
__device__ float g_bfuse[2 * 128];

// ---------------------------------------------------------------------------
// helpers
// ---------------------------------------------------------------------------
__device__ __forceinline__ float warp_sum(float v) {
#pragma unroll
    for (int o = 16; o; o >>= 1) v += __shfl_xor_sync(0xffffffffu, v, o);
    return v;
}
__device__ __forceinline__ float warp_max(float v) {
#pragma unroll
    for (int o = 16; o; o >>= 1) v = fmaxf(v, __shfl_xor_sync(0xffffffffu, v, o));
    return v;
}

// Pair-ownership GEMM core: lane owns output features (2*lane, 2*lane+1).
// Weights [c][f] canonical in smem -> weight pair is one LDS.64, conflict-free.
// Input rows read as broadcast float4 LDS. Bit-identical dot products vs the
// (lane, lane+32) split; only lane assignment differs.
template <int S>
__device__ __forceinline__ void mm64_core2(const float* __restrict__ in, int in_stride,
                                           const float* __restrict__ Wt, int wstride,
                                           int lane, float2* acc) {
#pragma unroll
    for (int s = 0; s < S; s++) { acc[s].x = 0.f; acc[s].y = 0.f; }
#pragma unroll
    for (int c4 = 0; c4 < 16; c4++) {
        float4 xv[S];
#pragma unroll
        for (int s = 0; s < S; s++)
            xv[s] = *reinterpret_cast<const float4*>(in + s * in_stride + (c4 << 2));
#pragma unroll
        for (int j = 0; j < 4; j++) {
            const float2 w = *reinterpret_cast<const float2*>(
                Wt + ((c4 << 2) + j) * wstride + 2 * lane);
#pragma unroll
            for (int s = 0; s < S; s++) {
                float xx = (j == 0) ? xv[s].x : (j == 1) ? xv[s].y : (j == 2) ? xv[s].z : xv[s].w;
                acc[s].x = fmaf(xx, w.x, acc[s].x);
                acc[s].y = fmaf(xx, w.y, acc[s].y);
            }
        }
    }
}

// Pair-ownership multi-matrix sweep over W ([c][WSTRIDE] layout): M weight
// streams at row offsets woff[m] (all even). One LDS.64 per stream per step.
template <int M, int WSTRIDE>
__device__ __forceinline__ void mmqkv_core2(const float* __restrict__ in,
                                            const float* __restrict__ Wq, const int* woff,
                                            int lane, float2 (*acc)[4]) {
#pragma unroll
    for (int m = 0; m < M; m++)
#pragma unroll
        for (int s = 0; s < 4; s++) { acc[m][s].x = 0.f; acc[m][s].y = 0.f; }
#pragma unroll
    for (int c4 = 0; c4 < 16; c4++) {
        float4 xv[4];
#pragma unroll
        for (int s = 0; s < 4; s++)
            xv[s] = *reinterpret_cast<const float4*>(in + s * 64 + (c4 << 2));
#pragma unroll
        for (int j = 0; j < 4; j++) {
            const float* wrow = Wq + ((c4 << 2) + j) * WSTRIDE;
            float2 w[M];
#pragma unroll
            for (int m = 0; m < M; m++)
                w[m] = *reinterpret_cast<const float2*>(wrow + woff[m] + 2 * lane);
#pragma unroll
            for (int s = 0; s < 4; s++) {
                float xx = (j == 0) ? xv[s].x : (j == 1) ? xv[s].y : (j == 2) ? xv[s].z : xv[s].w;
#pragma unroll
                for (int m = 0; m < M; m++) {
                    acc[m][s].x = fmaf(xx, w[m].x, acc[m][s].x);
                    acc[m][s].y = fmaf(xx, w[m].y, acc[m][s].y);
                }
            }
        }
    }
}

// LayerNorm over 64 features; lane owns (2*lane, 2*lane+1). g/b canonical.
__device__ __forceinline__ void ln_pair2(float r0, float r1,
                                         const float* __restrict__ g, const float* __restrict__ b,
                                         int lane, float& y0, float& y1) {
    float m = warp_sum(r0 + r1) * (1.f / 64.f);
    float d0 = r0 - m, d1 = r1 - m;
    float v = warp_sum(d0 * d0 + d1 * d1) * (1.f / 64.f);
    float inv = rsqrtf(v + EPS_LN);
    const float2 gv = *reinterpret_cast<const float2*>(g + 2 * lane);
    const float2 bv = *reinterpret_cast<const float2*>(b + 2 * lane);
    y0 = d0 * inv * gv.x + bv.x;
    y1 = d1 * inv * gv.y + bv.y;
}

// ---------------------------------------------------------------------------
// zero scratch
// ---------------------------------------------------------------------------
__global__ void zero_kernel() {
    size_t i = (size_t)blockIdx.x * blockDim.x + threadIdx.x;
    size_t stride = (size_t)gridDim.x * blockDim.x;
    float4* p = reinterpret_cast<float4*>(g_acc);
    size_t n4 = (2ull * NA_N * 256ull) / 4;
    for (size_t j = i; j < n4; j += stride) p[j] = make_float4(0.f, 0.f, 0.f, 0.f);
    for (size_t j = i; j < 2 * NA_N; j += stride) g_cnt[j] = 0;
}

// ---------------------------------------------------------------------------
// Fold b_proj into src k/v weights.
// ---------------------------------------------------------------------------
__global__ void fuse_kernel(const float* __restrict__ Wb, const float* __restrict__ bb,
                            const float* __restrict__ Wqkv, const float* __restrict__ bqkv) {
    const int t = blockIdx.x;
    const int tid = threadIdx.x;
    for (int idx = tid; idx < 64 * 128; idx += blockDim.x) {
        int c = idx >> 7, f = idx & 127;
        const float* wq = Wqkv + t * 12288 + (64 + f) * 64;
        const float* wb = Wb + t * 4096;
        float s = 0.f;
#pragma unroll 8
        for (int m = 0; m < 64; m++) s = fmaf(wq[m], wb[m * 64 + c], s);
        g_wfuse[t * 8192 + c * 128 + f] = s;
    }
    if (tid < 128) {
        const float* wq = Wqkv + t * 12288 + (64 + tid) * 64;
        const float* bbp = bb + t * 64;
        float s = bqkv[t * 192 + 64 + tid];
#pragma unroll 8
        for (int m = 0; m < 64; m++) s = fmaf(wq[m], bbp[m], s);
        g_bfuse[t * 128 + tid] = s;
    }
}

// ---------------------------------------------------------------------------
// Precompute per-(type, A-node): q,k,v of the dst tokens. One warp per node.
// Lane owns feature pair (2*lane, 2*lane+1) -> LDS.64 weights, STG.64 stores.
// ---------------------------------------------------------------------------
__global__ void __launch_bounds__(THREADS_BLK, 1) dstpre_kernel(
    const float* __restrict__ xA,
    const float* __restrict__ Wqkv, const float* __restrict__ bqkv) {
    extern __shared__ float smem[];
    float* sWq = smem;            // [c][192]
    float* sbq = sWq + 12288;     // 192
    float* bufs = sbq + 192;      // WARPS * 256

    const int type = blockIdx.x & 1;
    const int bidx = blockIdx.x >> 1;
    const int tid = threadIdx.x;
    {
        const float* p = Wqkv + type * 12288;
        for (int i = tid; i < 12288; i += THREADS_BLK) { int g = i >> 6, c = i & 63; sWq[c * 192 + g] = p[i]; }
        if (tid < 192) sbq[tid] = bqkv[type * 192 + tid];
    }
    __syncthreads();

    const int warp = tid >> 5, lane = tid & 31;
    float* buf = bufs + warp * 256;
    const int woff3[3] = {0, 64, 128};

    for (int n = bidx * WARPS_PER_BLK + warp; n < NA_N; n += NODE_STRIDE) {
        const float4* gx = reinterpret_cast<const float4*>(xA + (size_t)n * 256);
        reinterpret_cast<float4*>(buf)[lane]      = __ldg(gx + lane);
        reinterpret_cast<float4*>(buf)[lane + 32] = __ldg(gx + lane + 32);
        __syncwarp();
        float2 acc[3][4];
        mmqkv_core2<3, 192>(buf, sWq, woff3, lane, acc);
        float* outp = g_dstqkv + ((size_t)type * NA_N + n) * 768;
#pragma unroll
        for (int m = 0; m < 3; m++) {
            const float2 bv = *reinterpret_cast<const float2*>(sbq + woff3[m] + 2 * lane);
#pragma unroll
            for (int s = 0; s < 4; s++) {
                *reinterpret_cast<float2*>(outp + m * 256 + s * 64 + 2 * lane) =
                    make_float2(acc[m][s].x + bv.x, acc[m][s].y + bv.y);
            }
        }
        __syncwarp();
    }
}

// ---------------------------------------------------------------------------
// Precompute per-(type, src-node): k,v of projected src tokens, fused weights.
// ---------------------------------------------------------------------------
__global__ void __launch_bounds__(THREADS_BLK, 1) srcpre_kernel(
    const float* __restrict__ xA, const float* __restrict__ xB) {
    extern __shared__ float smem[];
    float* sWf = smem;            // [c][128]
    float* sbf = sWf + 8192;      // 128
    float* bufs = sbf + 128;      // WARPS * 256

    const int type = blockIdx.x & 1;
    const int bidx = blockIdx.x >> 1;
    const int tid = threadIdx.x;
    {
        const float* p = g_wfuse + type * 8192;
        for (int i = tid; i < 8192; i += THREADS_BLK) sWf[i] = p[i];
        if (tid < 128) sbf[tid] = g_bfuse[type * 128 + tid];
    }
    __syncthreads();

    const int warp = tid >> 5, lane = tid & 31;
    float* buf = bufs + warp * 256;
    const float* xsrc = type ? xA : xB;
    const int NSRC = NA_N;
    const int woff2[2] = {0, 64};

    for (int n = bidx * WARPS_PER_BLK + warp; n < NSRC; n += NODE_STRIDE) {
        const float4* gx = reinterpret_cast<const float4*>(xsrc + (size_t)n * 256);
        reinterpret_cast<float4*>(buf)[lane]      = __ldg(gx + lane);
        reinterpret_cast<float4*>(buf)[lane + 32] = __ldg(gx + lane + 32);
        __syncwarp();
        float2 acc[2][4];
        mmqkv_core2<2, 128>(buf, sWf, woff2, lane, acc);
        float* outp = g_srckv + ((size_t)type * NA_N + n) * 512;
#pragma unroll
        for (int m = 0; m < 2; m++) {
            const float2 bv = *reinterpret_cast<const float2*>(sbf + woff2[m] + 2 * lane);
#pragma unroll
            for (int s = 0; s < 4; s++) {
                *reinterpret_cast<float2*>(outp + m * 256 + s * 64 + 2 * lane) =
                    make_float2(acc[m][s].x + bv.x, acc[m][s].y + bv.y);
            }
        }
        __syncwarp();
    }
}

// ---------------------------------------------------------------------------
// per-edge: TWO edges per warp (exact R8 structure + pair feature ownership).
// k/v smem layout canonical (R8); attention identical to R8. GEMM path: lane
// owns features (2*lane, 2*lane+1) -> LDS.64 weights, LDG.64 residual,
// STS.64 stores, red.v2 scatter. g_acc stays canonical.
// Per-warp smem (2560 floats): qox[512] | kbuf[1024](ffb alias) | vbuf[1024]
// ---------------------------------------------------------------------------
__global__ void __launch_bounds__(THREADS_BLK, 1) edge_kernel(
    const float* __restrict__ xA,
    const int* __restrict__ e0, int E0,
    const int* __restrict__ e1, int E1,
    const float* __restrict__ Wo,  const float* __restrict__ bo,
    const float* __restrict__ g1,  const float* __restrict__ be1,
    const float* __restrict__ W1,  const float* __restrict__ bf1,
    const float* __restrict__ W2,  const float* __restrict__ bf2,
    const float* __restrict__ g2,  const float* __restrict__ be2) {
    extern __shared__ float smem[];
    float* sWo  = smem;              // [c][f]  64*64
    float* sW1  = sWo + 4096;        // [c][f]  64*64
    float* sW2  = sW1 + 4096;        // [f][c]  64*64
    float* sbo  = sW2 + 4096;        // 64
    float* sbf1 = sbo + 64;
    float* sbf2 = sbf1 + 64;
    float* sg1  = sbf2 + 64;
    float* sbe1 = sg1 + 64;
    float* sg2  = sbe1 + 64;
    float* sbe2 = sg2 + 64;
    float* bufs = sbe2 + 64;         // WARPS * 2560

    const int type = blockIdx.x & 1;
    const int bidx = blockIdx.x >> 1;
    const int tid = threadIdx.x;
    {
        const float* p = Wo + type * 4096;
        for (int i = tid; i < 4096; i += THREADS_BLK) { int f = i >> 6, c = i & 63; sWo[c * 64 + f] = p[i]; }
        p = W1 + type * 4096;
        for (int i = tid; i < 4096; i += THREADS_BLK) { int f = i >> 6, c = i & 63; sW1[c * 64 + f] = p[i]; }
        p = W2 + type * 4096;
        for (int i = tid; i < 4096; i += THREADS_BLK) { int c = i >> 6, f = i & 63; sW2[f * 64 + c] = p[i]; }
        if (tid < 64) sbo[tid]  = bo[type * 64 + tid];
        if (tid < 64) sbf1[tid] = bf1[type * 64 + tid];
        if (tid < 64) sbf2[tid] = bf2[type * 64 + tid];
        if (tid < 64) sg1[tid]  = g1[type * 64 + tid];
        if (tid < 64) sbe1[tid] = be1[type * 64 + tid];
        if (tid < 64) sg2[tid]  = g2[type * 64 + tid];
        if (tid < 64) sbe2[tid] = be2[type * 64 + tid];
        // zero per-warp buffers so an invalid tail edge computes on finite data
        for (int i = tid; i < WARPS_PER_BLK * 2560; i += THREADS_BLK) bufs[i] = 0.f;
    }
    __syncthreads();

    const int warp = tid >> 5, lane = tid & 31;
    const int eidx = lane >> 4, l16 = lane & 15;    // half-warp edge slot
    float* buf  = bufs + warp * 2560;
    float* qox  = buf;            // 512 (canonical layout, 2 edges)
    float* kbuf = buf + 512;      // 1024 (ffb aliases after attention)
    float* vbuf = buf + 1536;     // 1024
    float* ffb  = kbuf;           // 512 used

    const int* ei = type ? e1 : e0;
    const int  E  = type ? E1 : E0;
    float* accbase = g_acc + (size_t)type * NA_N * 256ull;
    int*   cntbase = g_cnt + type * NA_N;

    for (int e = bidx * (WARPS_PER_BLK * 2) + warp * 2; e < E; e += PAIR_STRIDE) {
        const bool v1 = (e + 1 < E);
        const int s0 = __ldg(ei + e);
        const int d0 = __ldg(ei + E + e);
        const int s1 = v1 ? __ldg(ei + e + 1) : s0;
        const int d1 = v1 ? __ldg(ei + E + e + 1) : d0;
        const int de = eidx ? d1 : d0;
        const int se = eidx ? s1 : s0;
        const float* dq_base = g_dstqkv + ((size_t)type * NA_N + de) * 768;

        // Gather k,v (dst+src) for own edge: 16 LDG.128 + 16 STS.128 per lane (2 edges)
        {
            const float4* gdq = reinterpret_cast<const float4*>(dq_base);
            const float4* gsk = reinterpret_cast<const float4*>(g_srckv + ((size_t)type * NA_N + se) * 512);
            float4* kb4 = reinterpret_cast<float4*>(kbuf + eidx * 512);
            float4* vb4 = reinterpret_cast<float4*>(vbuf + eidx * 512);
#pragma unroll
            for (int j = 0; j < 4; j++) {
                kb4[l16 + 16 * j]      = __ldg(gdq + 64  + l16 + 16 * j);
                vb4[l16 + 16 * j]      = __ldg(gdq + 128 + l16 + 16 * j);
                kb4[64 + l16 + 16 * j] = __ldg(gsk + l16 + 16 * j);
                vb4[64 + l16 + 16 * j] = __ldg(gsk + 64 + l16 + 16 * j);
            }
        }

        // xi residual prefetch into registers: coalesced LDG.64 (features 2*lane, 2*lane+1)
        float2 xr[8];
#pragma unroll
        for (int t = 0; t < 8; t++) {
            const int dd = (t >= 4) ? d1 : d0;
            xr[t] = __ldg(reinterpret_cast<const float2*>(
                xA + (size_t)dd * 256 + (t & 3) * 64 + 2 * lane));
        }
        __syncwarp();

        // attention: 32 lanes = 2 edges x 4 heads x 4 query tokens (exact R8).
        {
            const int h = (lane >> 2) & 3, s = lane & 3;
            const float4* qp4 = reinterpret_cast<const float4*>(dq_base + s * 64 + h * 16);
            float4 qa = __ldg(qp4), qb = __ldg(qp4 + 1), qc = __ldg(qp4 + 2), qd = __ldg(qp4 + 3);
            float q[16] = {qa.x, qa.y, qa.z, qa.w, qb.x, qb.y, qb.z, qb.w,
                           qc.x, qc.y, qc.z, qc.w, qd.x, qd.y, qd.z, qd.w};
            const float* kpe = kbuf + eidx * 512 + h * 16;
            const float* vpe = vbuf + eidx * 512 + h * 16;
            float scr[8];
#pragma unroll
            for (int t = 0; t < 8; t++) {
                const float* kp = kpe + t * 64;
                float a = 0.f;
#pragma unroll
                for (int d = 0; d < 16; d++) a = fmaf(q[d], kp[d], a);
                scr[t] = a * 0.25f;  // 1/sqrt(16)
            }
            float m = scr[0];
#pragma unroll
            for (int t = 1; t < 8; t++) m = fmaxf(m, scr[t]);
            float ssum = 0.f;
#pragma unroll
            for (int t = 0; t < 8; t++) { scr[t] = __expf(scr[t] - m); ssum += scr[t]; }
            float inv = 1.f / ssum;
            float o[16];
#pragma unroll
            for (int d = 0; d < 16; d++) o[d] = 0.f;
#pragma unroll
            for (int t = 0; t < 8; t++) {
                const float* vp = vpe + t * 64;
                float p = scr[t] * inv;
#pragma unroll
                for (int d = 0; d < 16; d++) o[d] = fmaf(p, vp[d], o[d]);
            }
            float* op = qox + eidx * 256 + s * 64 + h * 16;
#pragma unroll
            for (int d = 0; d < 16; d++) op[d] = o[d];
        }
        __syncwarp();

        // attn proj (S=8, both edges) + residual(regs) + LN1; rewrites qox
        {
            float2 acc[8];
            mm64_core2<8>(qox, 64, sWo, 64, lane, acc);
            __syncwarp();
            const float2 bv = *reinterpret_cast<const float2*>(sbo + 2 * lane);
#pragma unroll
            for (int t = 0; t < 8; t++) {
                float r0 = acc[t].x + bv.x + xr[t].x;
                float r1 = acc[t].y + bv.y + xr[t].y;
                float y0, y1;
                ln_pair2(r0, r1, sg1, sbe1, lane, y0, y1);
                *reinterpret_cast<float2*>(qox + t * 64 + 2 * lane) = make_float2(y0, y1);
            }
        }
        __syncwarp();

        // FF1 (relu): qox -> ffb (aliases kbuf; k is dead)
        {
            float2 acc[8];
            mm64_core2<8>(qox, 64, sW1, 64, lane, acc);
            const float2 bv = *reinterpret_cast<const float2*>(sbf1 + 2 * lane);
#pragma unroll
            for (int s = 0; s < 8; s++) {
                *reinterpret_cast<float2*>(ffb + s * 64 + 2 * lane) =
                    make_float2(fmaxf(acc[s].x + bv.x, 0.f), fmaxf(acc[s].y + bv.y, 0.f));
            }
        }
        __syncwarp();

        // FF2 + residual(qox) + LN2 -> vector atomic scatter (canonical layout;
        // lane's features 2*lane, 2*lane+1 are adjacent in g_acc)
        {
            float2 acc[8];
            mm64_core2<8>(ffb, 64, sW2, 64, lane, acc);
            const float2 bv = *reinterpret_cast<const float2*>(sbf2 + 2 * lane);
#pragma unroll
            for (int t = 0; t < 8; t++) {
                if (t < 4 || v1) {
                    const int dd = (t >= 4) ? d1 : d0;
                    float* accp = accbase + (size_t)dd * 256 + (t & 3) * 64;
                    const float2 xv = *reinterpret_cast<const float2*>(qox + t * 64 + 2 * lane);
                    float r0 = acc[t].x + bv.x + xv.x;
                    float r1 = acc[t].y + bv.y + xv.y;
                    float y0, y1;
                    ln_pair2(r0, r1, sg2, sbe2, lane, y0, y1);
                    asm volatile("red.global.add.v2.f32 [%0], {%1, %2};"
                                 :: "l"(accp + 2 * lane), "f"(y0), "f"(y1) : "memory");
                }
            }
            if (lane == 0) {
                atomicAdd(cntbase + d0, 1);
                if (v1) atomicAdd(cntbase + d1, 1);
            }
        }
        __syncwarp();
    }
}

// ---------------------------------------------------------------------------
// final: mean across edge types, Wout per token, sum over tokens, softmax(32)
// one warp per node, 4 nodes per block (g_acc canonical -> unchanged from R8)
// ---------------------------------------------------------------------------
__global__ void __launch_bounds__(128) out_kernel(const float* __restrict__ Wout,
                                                  const float* __restrict__ bout,
                                                  float* __restrict__ out) {
    __shared__ float sW[2048];   // [c][o]
    __shared__ float sb[32];
    __shared__ float comb[4][256];
    const int tid = threadIdx.x;
    for (int i = tid; i < 2048; i += 128) { int o = i >> 6, c = i & 63; sW[c * 32 + o] = Wout[i]; }
    if (tid < 32) sb[tid] = bout[tid];
    __syncthreads();

    const int warp = tid >> 5, lane = tid & 31;
    const int n = blockIdx.x * 4 + warp;
    if (n >= NA_N) return;

    const int c0 = g_cnt[n], c1 = g_cnt[NA_N + n];
    const float i0 = (c0 > 0) ? 0.5f / (float)c0 : 0.f;
    const float i1 = (c1 > 0) ? 0.5f / (float)c1 : 0.f;
    const float* a0 = g_acc + (size_t)n * 256;
    const float* a1 = g_acc + (size_t)NA_N * 256 + (size_t)n * 256;
    float* cb = comb[warp];
#pragma unroll
    for (int j = 0; j < 8; j++) {
        int i = lane + 32 * j;
        cb[i] = a0[i] * i0 + a1[i] * i1;
    }
    __syncwarp();

    float h = 0.f;
#pragma unroll 4
    for (int i = 0; i < 256; i++) {
        int c = i & 63;
        h = fmaf(cb[i], sW[c * 32 + lane], h);
    }
    h += 4.f * sb[lane];

    float m = warp_max(h);
    float ex = __expf(h - m);
    float s = warp_sum(ex);
    out[(size_t)n * 32 + lane] = ex / s;
}

// ---------------------------------------------------------------------------
extern "C" void kernel_launch(void* const* d_in, const int* in_sizes, int n_in,
                              void* d_out, int out_size) {
    const float* xA   = (const float*)d_in[0];
    const float* xB   = (const float*)d_in[1];
    const int*   e0   = (const int*)d_in[2];
    const int*   e1   = (const int*)d_in[3];
    const float* Wb   = (const float*)d_in[4];
    const float* bb   = (const float*)d_in[5];
    const float* Wqkv = (const float*)d_in[6];
    const float* bqkv = (const float*)d_in[7];
    const float* Wo   = (const float*)d_in[8];
    const float* bo   = (const float*)d_in[9];
    const float* g1   = (const float*)d_in[10];
    const float* be1  = (const float*)d_in[11];
    const float* W1   = (const float*)d_in[12];
    const float* bf1  = (const float*)d_in[13];
    const float* W2   = (const float*)d_in[14];
    const float* bf2  = (const float*)d_in[15];
    const float* g2   = (const float*)d_in[16];
    const float* be2  = (const float*)d_in[17];
    const float* Wout = (const float*)d_in[18];
    const float* bout = (const float*)d_in[19];

    const int E0 = in_sizes[2] / 2;
    const int E1 = in_sizes[3] / 2;

    const int dst_smem  = (12288 + 192 + WARPS_PER_BLK * 256) * 4;
    const int src_smem  = (8192 + 128 + WARPS_PER_BLK * 256) * 4;
    const int edge_smem = (3 * 4096 + 7 * 64 + WARPS_PER_BLK * 2560) * 4;   // 173,824 B
    cudaFuncSetAttribute(dstpre_kernel, cudaFuncAttributeMaxDynamicSharedMemorySize, dst_smem);
    cudaFuncSetAttribute(srcpre_kernel, cudaFuncAttributeMaxDynamicSharedMemorySize, src_smem);
    cudaFuncSetAttribute(edge_kernel,   cudaFuncAttributeMaxDynamicSharedMemorySize, edge_smem);

    zero_kernel<<<2048, 256>>>();
    fuse_kernel<<<2, 256>>>(Wb, bb, Wqkv, bqkv);
    dstpre_kernel<<<2 * 148, THREADS_BLK, dst_smem>>>(xA, Wqkv, bqkv);
    srcpre_kernel<<<2 * 148, THREADS_BLK, src_smem>>>(xA, xB);
    edge_kernel<<<2 * EDGE_BLOCKS, THREADS_BLK, edge_smem>>>(
        xA, e0, E0, e1, E1,
        Wo, bo, g1, be1, W1, bf1, W2, bf2, g2, be2);
    out_kernel<<<(NA_N + 3) / 4, 128>>>(Wout, bout, (float*)d_out);
}